// round 7
// baseline (speedup 1.0000x reference)
#include <cuda_runtime.h>
#include <cstdint>

// LWTA over groups of 4 consecutive fp32 units. One float4 == one pool group.
// Keep first max (strict > matches jnp.argmax first-tie), zero rest.
//
// Persistent grid-stride config: grid = 148 SMs x 8 = 1184 blocks, single
// wave; each block loops with grid-wide stride over unroll-4 chunks.
// Per-iteration pattern identical to the proven R2 schedule: 256 threads,
// 4 front-batched LDG.128 (512B contiguous per warp), 4 STG.128.
// Targets the ~2-3us of wave-transition/tail overhead left above the
// 268MB/~7.5TB/s HBM roofline (~35.5us kernel floor).

__device__ __forceinline__ float4 lwta4(float4 v) {
    float m = v.x; int idx = 0;
    if (v.y > m) { m = v.y; idx = 1; }
    if (v.z > m) { m = v.z; idx = 2; }
    if (v.w > m) { m = v.w; idx = 3; }
    float4 r;
    r.x = (idx == 0) ? v.x : 0.0f;
    r.y = (idx == 1) ? v.y : 0.0f;
    r.z = (idx == 2) ? v.z : 0.0f;
    r.w = (idx == 3) ? v.w : 0.0f;
    return r;
}

__global__ void __launch_bounds__(256) lwta_kernel(const float4* __restrict__ in,
                                                   float4* __restrict__ out,
                                                   int n_groups) {
    const int BS = 256;
    const int U = 4;
    const int CHUNK = BS * U;                     // 1024 groups per chunk
    int stride = gridDim.x * CHUNK;
    // full chunks via grid-stride loop
    for (int base = blockIdx.x * CHUNK; base + CHUNK <= n_groups; base += stride) {
        int t = base + threadIdx.x;
        float4 v[U];
        #pragma unroll
        for (int k = 0; k < U; k++) v[k] = __ldcs(&in[t + k * BS]);
        #pragma unroll
        for (int k = 0; k < U; k++) __stcs(&out[t + k * BS], lwta4(v[k]));
    }
    // tail (n_groups not a multiple of CHUNK) — handled by first blocks
    int rem_start = (n_groups / CHUNK) * CHUNK;
    int rem = n_groups - rem_start;
    if (rem > 0 && blockIdx.x == 0) {
        for (int i = rem_start + threadIdx.x; i < n_groups; i += BS)
            __stcs(&out[i], lwta4(__ldcs(&in[i])));
    }
}

extern "C" void kernel_launch(void* const* d_in, const int* in_sizes, int n_in,
                              void* d_out, int out_size) {
    const float4* in = (const float4*)d_in[0];
    float4* out = (float4*)d_out;
    int n = in_sizes[0];               // 4096*8192 = 33554432 floats
    int n_groups = n / 4;              // 8388608 float4 groups
    int blocks = 148 * 8;              // 1184: one resident wave
    lwta_kernel<<<blocks, 256>>>(in, out, n_groups);
}

// round 8
// speedup vs baseline: 1.0675x; 1.0675x over previous
#include <cuda_runtime.h>
#include <cstdint>

// LWTA over groups of 4 consecutive fp32 units. One float4 == one pool group.
// Keep first max (strict > matches jnp.argmax first-tie), zero rest.
//
// FINAL: flat grid, 256 threads, block-strided unroll-8, 8 front-batched
// LDG.128 per thread (every access 512B-contiguous per warp). Grid=4096.
// Best measured wall config (R3: 44.70us). Kernel is pinned at the HBM
// roofline: 268MB mandatory traffic @ ~7.2-7.5TB/s effective (~35.5us floor).
// Ruled out: unroll-4 flat (45.1-45.5), 512-thread blocks (L1tex queue
// contention, 45.5), persistent grid-stride (loop overhead, 48.1).

__device__ __forceinline__ float4 lwta4(float4 v) {
    float m = v.x; int idx = 0;
    if (v.y > m) { m = v.y; idx = 1; }
    if (v.z > m) { m = v.z; idx = 2; }
    if (v.w > m) { m = v.w; idx = 3; }
    float4 r;
    r.x = (idx == 0) ? v.x : 0.0f;
    r.y = (idx == 1) ? v.y : 0.0f;
    r.z = (idx == 2) ? v.z : 0.0f;
    r.w = (idx == 3) ? v.w : 0.0f;
    return r;
}

__global__ void __launch_bounds__(256) lwta_kernel(const float4* __restrict__ in,
                                                   float4* __restrict__ out,
                                                   int n_groups) {
    const int UNROLL = 8;
    const int BS = 256;
    int block_base = blockIdx.x * (BS * UNROLL);
    int tid = block_base + threadIdx.x;

    if (block_base + BS * UNROLL <= n_groups) {
        float4 v[UNROLL];
        #pragma unroll
        for (int k = 0; k < UNROLL; k++)
            v[k] = __ldcs(&in[tid + k * BS]);
        #pragma unroll
        for (int k = 0; k < UNROLL; k++)
            __stcs(&out[tid + k * BS], lwta4(v[k]));
    } else {
        #pragma unroll
        for (int k = 0; k < UNROLL; k++) {
            int i = tid + k * BS;
            if (i < n_groups)
                __stcs(&out[i], lwta4(__ldcs(&in[i])));
        }
    }
}

extern "C" void kernel_launch(void* const* d_in, const int* in_sizes, int n_in,
                              void* d_out, int out_size) {
    const float4* in = (const float4*)d_in[0];
    float4* out = (float4*)d_out;
    int n = in_sizes[0];              // 4096*8192 = 33554432 floats
    int n_groups = n / 4;             // 8388608 float4 groups
    int groups_per_block = 256 * 8;   // unroll 8
    int blocks = (n_groups + groups_per_block - 1) / groups_per_block;  // 4096
    lwta_kernel<<<blocks, 256>>>(in, out, n_groups);
}